// round 12
// baseline (speedup 1.0000x reference)
#include <cuda_runtime.h>
#include <cuda_fp16.h>
#include <cuda_bf16.h>
#include <math.h>
#include <stdint.h>

#define BB 32
#define NN 1024
#define HH 256

// Scratch (__device__ globals; no allocations allowed)
static __device__ __half        g_WhH[BB * NN * HH];   // 16 MB fp16 Wh
static __device__ float         g_s1[BB * NN];
static __device__ float         g_s2[BB * NN];
static __device__ __nv_bfloat16 g_WT[4][HH * HH];      // WiH, WiL, WcH, WcL, transposed [n][k]

// ---------------------------------------------------------------------------
__device__ __forceinline__ uint32_t smem_u32(const void* p) {
    uint32_t a;
    asm("{ .reg .u64 t; cvta.to.shared.u64 t, %1; cvt.u32.u64 %0, t; }" : "=r"(a) : "l"(p));
    return a;
}

#define LDSM_X4(r0, r1, r2, r3, addr) \
    asm volatile("ldmatrix.sync.aligned.m8n8.x4.shared.b16 {%0,%1,%2,%3}, [%4];" \
                 : "=r"(r0), "=r"(r1), "=r"(r2), "=r"(r3) : "r"(addr))

#define LDSM_X4_T(r0, r1, r2, r3, addr) \
    asm volatile("ldmatrix.sync.aligned.m8n8.x4.trans.shared.b16 {%0,%1,%2,%3}, [%4];" \
                 : "=r"(r0), "=r"(r1), "=r"(r2), "=r"(r3) : "r"(addr))

#define MMA_BF16(d, a, b0r, b1r) \
    asm volatile("mma.sync.aligned.m16n8k16.row.col.f32.bf16.bf16.f32 " \
                 "{%0,%1,%2,%3}, {%4,%5,%6,%7}, {%8,%9}, {%0,%1,%2,%3};" \
                 : "+f"((d)[0]), "+f"((d)[1]), "+f"((d)[2]), "+f"((d)[3]) \
                 : "r"((a)[0]), "r"((a)[1]), "r"((a)[2]), "r"((a)[3]), \
                   "r"(b0r), "r"(b1r))

#define MMA_F16(d, a, b0r, b1r) \
    asm volatile("mma.sync.aligned.m16n8k16.row.col.f32.f16.f16.f32 " \
                 "{%0,%1,%2,%3}, {%4,%5,%6,%7}, {%8,%9}, {%0,%1,%2,%3};" \
                 : "+f"((d)[0]), "+f"((d)[1]), "+f"((d)[2]), "+f"((d)[3]) \
                 : "r"((a)[0]), "r"((a)[1]), "r"((a)[2]), "r"((a)[3]), \
                   "r"(b0r), "r"(b1r))

#define CP16(dst, src) \
    asm volatile("cp.async.cg.shared.global [%0], [%1], 16;" :: "r"(dst), "l"(src))
#define CP_COMMIT() asm volatile("cp.async.commit_group;" ::: "memory")

// ---------------------------------------------------------------------------
// Kernel 0: split W_i/W_c into transposed bf16 hi/lo: WT[n][k] = W[k][n]
// ---------------------------------------------------------------------------
__global__ __launch_bounds__(256) void wsplit_kernel(
    const float* __restrict__ Wi, const float* __restrict__ Wc)
{
    int idx = blockIdx.x * 256 + threadIdx.x;
    int which = idx >> 16;
    int e = idx & 65535;
    int n = e >> 8, k = e & 255;
    const float* W = which ? Wc : Wi;
    float x = W[k * HH + n];
    __nv_bfloat16 h = __float2bfloat16(x);
    __nv_bfloat16 lo = __float2bfloat16(x - __bfloat162float(h));
    g_WT[which * 2][n * HH + k] = h;
    g_WT[which * 2 + 1][n * HH + k] = lo;
}

// ---------------------------------------------------------------------------
// Kernel 1 (r11-validated, unchanged): mma.sync bf16 3-term split GEMM,
// 128x256 per CTA, 512 threads, double-buffered smem + register prefetch.
// Fused s1/s2 dots + fp16 Wh store.
// ---------------------------------------------------------------------------
#define PADK 40
#define ABUF (2 * 128 * PADK * 2)
#define BBUF (2 * 256 * PADK * 2)
#define OFF_A   0
#define OFF_B   (2 * ABUF)
#define OFF_AV  (OFF_B + 2 * BBUF)
#define OFF_RED (OFF_AV + 512 * 4)
#define SMEM_TOT (OFF_RED + 4 * 128 * 2 * 4)

__global__ __launch_bounds__(512) void gemm_kernel(
    const float* __restrict__ inp, const int* __restrict__ l,
    const float* __restrict__ avec)
{
    extern __shared__ char smem[];
    const uint32_t sbA = smem_u32(smem) + OFF_A;
    const uint32_t sbB = smem_u32(smem) + OFF_B;
    float* sAv  = (float*)(smem + OFF_AV);
    float* sRed = (float*)(smem + OFF_RED);

    const int tid = threadIdx.x, lane = tid & 31, wid = tid >> 5;
    const int warpRow = wid >> 2, warpCol = wid & 3;
    const int rowTile = blockIdx.x * 128;
    const int b = rowTile >> 10;
    const int n0 = rowTile & 1023;
    const int l0 = l[2 * b], l1 = l[2 * b + 1];
    const bool mixed = (l0 > n0 && l0 < n0 + 128) || (l1 > n0 && l1 < n0 + 128);
    const bool sel0  = (n0 >= l0 && n0 < l1);
    const int npass  = mixed ? 2 : 1;

    sAv[tid] = avec[tid];

    for (int pass = 0; pass < npass; ++pass) {
        const bool useWi = mixed ? (pass == 0) : sel0;
        const __nv_bfloat16* __restrict__ Bh = g_WT[useWi ? 0 : 2];
        const __nv_bfloat16* __restrict__ Bl = g_WT[useWi ? 1 : 3];

        float acc[2][8][4];
        #pragma unroll
        for (int mt = 0; mt < 2; ++mt)
            #pragma unroll
            for (int nt = 0; nt < 8; ++nt)
                #pragma unroll
                for (int e = 0; e < 4; ++e) acc[mt][nt][e] = 0.0f;

        float4 aReg[2];
        int4   bhReg[2], blReg[2];

        auto load_regs = [&](int kc) {
            const int k0 = kc * 32;
            #pragma unroll
            for (int it = 0; it < 2; ++it) {
                int f = tid + it * 512;
                int r = f >> 3, c4 = (f & 7) * 4;
                aReg[it] = *(const float4*)(inp + (size_t)(rowTile + r) * HH + k0 + c4);
            }
            #pragma unroll
            for (int it = 0; it < 2; ++it) {
                int gI = tid + it * 512;
                int r = gI >> 2, c8 = (gI & 3) * 8;
                bhReg[it] = *(const int4*)(Bh + (size_t)r * HH + k0 + c8);
                blReg[it] = *(const int4*)(Bl + (size_t)r * HH + k0 + c8);
            }
        };

        load_regs(0);

        for (int kc = 0; kc < 8; ++kc) {
            const int s = kc & 1;
            const uint32_t aS = sbA + (uint32_t)s * ABUF;
            const uint32_t bS = sbB + (uint32_t)s * BBUF;

            #pragma unroll
            for (int it = 0; it < 2; ++it) {
                int f = tid + it * 512;
                int r = f >> 3, c4 = (f & 7) * 4;
                float xv[4] = {aReg[it].x, aReg[it].y, aReg[it].z, aReg[it].w};
                unsigned short h[4], q[4];
                #pragma unroll
                for (int e = 0; e < 4; ++e) {
                    __nv_bfloat16 bh = __float2bfloat16(xv[e]);
                    h[e] = __bfloat16_as_ushort(bh);
                    q[e] = __bfloat16_as_ushort(
                        __float2bfloat16(xv[e] - __bfloat162float(bh)));
                }
                uint2 hv = make_uint2(h[0] | ((uint32_t)h[1] << 16),
                                      h[2] | ((uint32_t)h[3] << 16));
                uint2 lv = make_uint2(q[0] | ((uint32_t)q[1] << 16),
                                      q[2] | ((uint32_t)q[3] << 16));
                *(uint2*)(smem + OFF_A + s * ABUF + ((size_t)r * PADK + c4) * 2) = hv;
                *(uint2*)(smem + OFF_A + s * ABUF + ((size_t)(128 + r) * PADK + c4) * 2) = lv;
            }
            #pragma unroll
            for (int it = 0; it < 2; ++it) {
                int gI = tid + it * 512;
                int r = gI >> 2, c8 = (gI & 3) * 8;
                *(int4*)(smem + OFF_B + s * BBUF + ((size_t)r * PADK + c8) * 2) = bhReg[it];
                *(int4*)(smem + OFF_B + s * BBUF + ((size_t)(256 + r) * PADK + c8) * 2) = blReg[it];
            }
            __syncthreads();

            if (kc < 7) load_regs(kc + 1);

            #pragma unroll
            for (int ks = 0; ks < 2; ++ks) {
                const int kk = ks * 16;
                uint32_t ah[2][4], al[2][4];
                #pragma unroll
                for (int mt = 0; mt < 2; ++mt) {
                    int row = warpRow * 32 + mt * 16 + (lane & 15);
                    int kcol = kk + (lane >> 4) * 8;
                    uint32_t ad = aS + (uint32_t)(row * PADK + kcol) * 2;
                    LDSM_X4(ah[mt][0], ah[mt][1], ah[mt][2], ah[mt][3], ad);
                    LDSM_X4(al[mt][0], al[mt][1], al[mt][2], al[mt][3],
                            ad + 128 * PADK * 2);
                }
                #pragma unroll
                for (int p = 0; p < 4; ++p) {
                    int row = warpCol * 64 + p * 16 + (lane & 7) + ((lane >> 4) << 3);
                    int kcol = kk + (((lane >> 3) & 1) << 3);
                    uint32_t bd = bS + (uint32_t)(row * PADK + kcol) * 2;
                    uint32_t bh[4], bl[4];
                    LDSM_X4(bh[0], bh[1], bh[2], bh[3], bd);
                    LDSM_X4(bl[0], bl[1], bl[2], bl[3], bd + 256 * PADK * 2);
                    #pragma unroll
                    for (int mt = 0; mt < 2; ++mt) {
                        MMA_BF16(acc[mt][2 * p],     ah[mt], bh[0], bh[1]);
                        MMA_BF16(acc[mt][2 * p],     al[mt], bh[0], bh[1]);
                        MMA_BF16(acc[mt][2 * p],     ah[mt], bl[0], bl[1]);
                        MMA_BF16(acc[mt][2 * p + 1], ah[mt], bh[2], bh[3]);
                        MMA_BF16(acc[mt][2 * p + 1], al[mt], bh[2], bh[3]);
                        MMA_BF16(acc[mt][2 * p + 1], ah[mt], bl[2], bl[3]);
                    }
                }
            }
        }

        __syncthreads();
        const int g = lane >> 2, qc = (lane & 3) * 2;
        #pragma unroll
        for (int mt = 0; mt < 2; ++mt) {
            int lr0 = warpRow * 32 + mt * 16 + g;
            int lr1 = lr0 + 8;
            int gr0 = rowTile + lr0, gr1 = rowTile + lr1;
            int nr0 = n0 + lr0, nr1 = n0 + lr1;
            bool dw0 = !mixed || (((nr0 >= l0) && (nr0 < l1)) == useWi);
            bool dw1 = !mixed || (((nr1 >= l0) && (nr1 < l1)) == useWi);
            float s1r0 = 0, s2r0 = 0, s1r1 = 0, s2r1 = 0;
            #pragma unroll
            for (int nt = 0; nt < 8; ++nt) {
                int col = warpCol * 64 + nt * 8 + qc;
                float a0 = sAv[col], a1 = sAv[col + 1];
                float b0 = sAv[256 + col], b1 = sAv[256 + col + 1];
                float c0 = acc[mt][nt][0], c1 = acc[mt][nt][1];
                float c2 = acc[mt][nt][2], c3 = acc[mt][nt][3];
                s1r0 = fmaf(c0, a0, fmaf(c1, a1, s1r0));
                s2r0 = fmaf(c0, b0, fmaf(c1, b1, s2r0));
                s1r1 = fmaf(c2, a0, fmaf(c3, a1, s1r1));
                s2r1 = fmaf(c2, b0, fmaf(c3, b1, s2r1));
                if (dw0)
                    *(__half2*)(g_WhH + (size_t)gr0 * HH + col) = __floats2half2_rn(c0, c1);
                if (dw1)
                    *(__half2*)(g_WhH + (size_t)gr1 * HH + col) = __floats2half2_rn(c2, c3);
            }
            #pragma unroll
            for (int d = 1; d <= 2; d <<= 1) {
                s1r0 += __shfl_xor_sync(0xffffffffu, s1r0, d);
                s2r0 += __shfl_xor_sync(0xffffffffu, s2r0, d);
                s1r1 += __shfl_xor_sync(0xffffffffu, s1r1, d);
                s2r1 += __shfl_xor_sync(0xffffffffu, s2r1, d);
            }
            if ((lane & 3) == 0) {
                sRed[(warpCol * 128 + lr0) * 2 + 0] = s1r0;
                sRed[(warpCol * 128 + lr0) * 2 + 1] = s2r0;
                sRed[(warpCol * 128 + lr1) * 2 + 0] = s1r1;
                sRed[(warpCol * 128 + lr1) * 2 + 1] = s2r1;
            }
        }
        __syncthreads();
        if (tid < 128) {
            int grow = rowTile + tid;
            int nrow = n0 + tid;
            bool dw = !mixed || (((nrow >= l0) && (nrow < l1)) == useWi);
            if (dw) {
                float v1 = 0, v2 = 0;
                #pragma unroll
                for (int wc = 0; wc < 4; ++wc) {
                    v1 += sRed[(wc * 128 + tid) * 2 + 0];
                    v2 += sRed[(wc * 128 + tid) * 2 + 1];
                }
                g_s1[grow] = v1;
                g_s2[grow] = v2;
            }
        }
        __syncthreads();
    }
}

// ---------------------------------------------------------------------------
// Kernel 2 (NEW): fused online-softmax attention + aggregation + elu.
// 128 rows x 256 cols per CTA, 512 threads, flash-style over 16 K-chunks of 64.
// Scores computed in-kernel from A + s1/s2; weights -> fp16 smem mma operand.
// MMA fragment code identical to the r10-validated bmm.
// ---------------------------------------------------------------------------
#define FPADK 72
#define F_SA32 (128 * 68 * 4)                 // 34816 per stage
#define F_OFF_A32 0
#define F_OFF_WH  (2 * F_SA32)                // 69632
#define F_SWH  (64 * 264 * 2)                 // 33792 per stage
#define F_OFF_ATT (F_OFF_WH + 2 * F_SWH)      // 137216
#define F_OFF_S2  (F_OFF_ATT + 128 * FPADK * 2)   // 155648
#define F_OFF_S1  (F_OFF_S2 + 4096)           // 159744
#define F_OFF_M   (F_OFF_S1 + 512)            // 160256
#define F_OFF_Z   (F_OFF_M + 512)             // 160768
#define F_OFF_SC  (F_OFF_Z + 512)             // 161280
#define FSMEM_TOT (F_OFF_SC + 512)            // 161792

__global__ __launch_bounds__(512) void fused_attn_kernel(
    const float* __restrict__ A, float* __restrict__ out)
{
    extern __shared__ char fsm[];
    const uint32_t attBase = smem_u32(fsm) + F_OFF_ATT;
    const uint32_t whBase  = smem_u32(fsm) + F_OFF_WH;
    const uint32_t a32Base = smem_u32(fsm) + F_OFF_A32;
    float* s2s = (float*)(fsm + F_OFF_S2);
    float* s1s = (float*)(fsm + F_OFF_S1);
    float* smM = (float*)(fsm + F_OFF_M);
    float* smZ = (float*)(fsm + F_OFF_Z);
    float* smS = (float*)(fsm + F_OFF_SC);

    const int tid = threadIdx.x, lane = tid & 31, wid = tid >> 5;
    const int warpRow = wid >> 2, warpCol = wid & 3;
    const int b  = blockIdx.x >> 3;
    const int rt = (blockIdx.x & 7) * 128;
    const float* Ab  = A + ((size_t)b * NN + rt) * NN;
    const __half* WhB = g_WhH + (size_t)b * NN * HH;

    // preload s1/s2, init state
    s2s[tid]       = g_s2[(size_t)b * NN + tid];
    s2s[512 + tid] = g_s2[(size_t)b * NN + 512 + tid];
    if (tid < 128) {
        s1s[tid] = g_s1[(size_t)b * NN + rt + tid];
        smM[tid] = -INFINITY;
        smZ[tid] = 0.0f;
    }

    float acc[2][8][4];
    #pragma unroll
    for (int mt = 0; mt < 2; ++mt)
        #pragma unroll
        for (int nt = 0; nt < 8; ++nt)
            #pragma unroll
            for (int e = 0; e < 4; ++e) acc[mt][nt][e] = 0.0f;

    auto load_stage = [&](int kc, int s) {
        const int k0 = kc * 64;
        uint32_t aS = a32Base + (uint32_t)s * F_SA32;
        uint32_t bS = whBase + (uint32_t)s * F_SWH;
        #pragma unroll
        for (int it = 0; it < 4; ++it) {
            int f = tid + it * 512;                 // 0..2047: 128 rows x 16 segs
            int r = f >> 4, sg = f & 15;
            CP16(aS + (uint32_t)(r * 272 + sg * 16),
                 Ab + (size_t)r * NN + k0 + sg * 4);
        }
        #pragma unroll
        for (int it = 0; it < 4; ++it) {
            int f = tid + it * 512;                 // 0..2047: 64 rows x 32 segs
            int r = f >> 5, c = (f & 31) * 8;
            CP16(bS + (uint32_t)(r * 264 + c) * 2,
                 WhB + (size_t)(k0 + r) * HH + c);
        }
        CP_COMMIT();
    };

    load_stage(0, 0);

    const int sr = tid >> 2;            // score row 0..127
    const int sq = tid & 3;             // quarter (16 cols)
    const int i_node = rt + sr;
    const float L2E = 1.44269504f;

    for (int kc = 0; kc < 16; ++kc) {
        const int s = kc & 1;
        const int k0 = kc * 64;
        if (kc + 1 < 16) {
            load_stage(kc + 1, s ^ 1);
            asm volatile("cp.async.wait_group 1;" ::: "memory");
        } else {
            asm volatile("cp.async.wait_group 0;" ::: "memory");
        }
        __syncthreads();   // A32[s], Wh[s] ready; prior chunk fully consumed

        // ---- score phase ----
        {
            const float* arow = (const float*)(fsm + F_OFF_A32 + s * F_SA32) + sr * 68 + sq * 16;
            const float s1v = s1s[sr];
            float xs[16];
            unsigned mask = 0;
            float lmax = -INFINITY;
            #pragma unroll
            for (int c4 = 0; c4 < 4; ++c4) {
                float4 av = *(const float4*)(arow + c4 * 4);
                float4 sv = *(const float4*)(s2s + k0 + sq * 16 + c4 * 4);
                float aa[4] = {av.x, av.y, av.z, av.w};
                float ss[4] = {sv.x, sv.y, sv.z, sv.w};
                #pragma unroll
                for (int e = 0; e < 4; ++e) {
                    int idx = c4 * 4 + e;
                    int j = k0 + sq * 16 + idx;
                    float aval = aa[e] + ((j == i_node) ? 1.0f : 0.0f);
                    if (aval > 0.0f) {
                        float x = (s1v + ss[e]) * aval;
                        x = (x > 0.0f) ? x : 0.2f * x;     // leaky relu
                        xs[idx] = x;
                        mask |= (1u << idx);
                        lmax = fmaxf(lmax, x);
                    }
                }
            }
            float rm = lmax;
            rm = fmaxf(rm, __shfl_xor_sync(0xffffffffu, rm, 1));
            rm = fmaxf(rm, __shfl_xor_sync(0xffffffffu, rm, 2));
            const float m_old = smM[sr];
            const float z_old = smZ[sr];
            const float m_new = fmaxf(m_old, rm);
            const float scale = (m_new == -INFINITY) ? 1.0f : __expf(m_old - m_new);
            __syncwarp(0xffffffffu);   // old m/Z read by all 4 before q0 writes

            uint32_t wpk[8];
            float zs = 0.0f;
            #pragma unroll
            for (int p = 0; p < 8; ++p) {
                float e0 = (mask & (1u << (2 * p)))     ? (xs[2 * p] - m_new) * L2E     : -20000.0f;
                float e1 = (mask & (1u << (2 * p + 1))) ? (xs[2 * p + 1] - m_new) * L2E : -20000.0f;
                __half2 hin = __floats2half2_rn(e0, e1);
                uint32_t uin = *reinterpret_cast<uint32_t*>(&hin);
                uint32_t uout;
                asm("ex2.approx.f16x2 %0, %1;" : "=r"(uout) : "r"(uin));
                wpk[p] = uout;
                __half2 hw = *reinterpret_cast<__half2*>(&uout);
                float2 fw = __half22float2(hw);
                zs += fw.x + fw.y;
            }
            zs += __shfl_xor_sync(0xffffffffu, zs, 1);
            zs += __shfl_xor_sync(0xffffffffu, zs, 2);

            char* attp = fsm + F_OFF_ATT + sr * (FPADK * 2) + sq * 32;
            *(int4*)attp        = make_int4(wpk[0], wpk[1], wpk[2], wpk[3]);
            *(int4*)(attp + 16) = make_int4(wpk[4], wpk[5], wpk[6], wpk[7]);

            if (sq == 0) {
                smM[sr] = m_new;
                smS[sr] = scale;
                smZ[sr] = z_old * scale + zs;
            }
        }
        __syncthreads();   // att tile + scales ready

        // ---- rescale acc ----
        {
            const int g = lane >> 2;
            #pragma unroll
            for (int mt = 0; mt < 2; ++mt) {
                int lr0 = warpRow * 32 + mt * 16 + g;
                float sc0 = smS[lr0], sc1 = smS[lr0 + 8];
                #pragma unroll
                for (int nt = 0; nt < 8; ++nt) {
                    acc[mt][nt][0] *= sc0; acc[mt][nt][1] *= sc0;
                    acc[mt][nt][2] *= sc1; acc[mt][nt][3] *= sc1;
                }
            }
        }

        // ---- MMA (identical fragment code to validated bmm) ----
        const uint32_t bS = whBase + (uint32_t)s * F_SWH;
        #pragma unroll
        for (int ks = 0; ks < 4; ++ks) {
            const int kk = ks * 16;
            uint32_t a[2][4];
            #pragma unroll
            for (int mt = 0; mt < 2; ++mt) {
                int row = warpRow * 32 + mt * 16 + (lane & 15);
                int kcol = kk + (lane >> 4) * 8;
                LDSM_X4(a[mt][0], a[mt][1], a[mt][2], a[mt][3],
                        attBase + (uint32_t)(row * FPADK + kcol) * 2);
            }
            #pragma unroll
            for (int p = 0; p < 4; ++p) {
                int n = warpCol * 64 + p * 16;
                int krow = kk + (lane & 15);
                int col = n + ((lane >> 4) << 3);
                uint32_t bfr[4];
                LDSM_X4_T(bfr[0], bfr[1], bfr[2], bfr[3],
                          bS + (uint32_t)(krow * 264 + col) * 2);
                #pragma unroll
                for (int mt = 0; mt < 2; ++mt) {
                    MMA_F16(acc[mt][2 * p],     a[mt], bfr[0], bfr[1]);
                    MMA_F16(acc[mt][2 * p + 1], a[mt], bfr[2], bfr[3]);
                }
            }
        }
        __syncthreads();   // att/stage reusable next iteration
    }

    // ---- epilogue: normalize by Z, elu, store ----
    const int g = lane >> 2, qc = (lane & 3) * 2;
    #pragma unroll
    for (int mt = 0; mt < 2; ++mt) {
        int lr0 = warpRow * 32 + mt * 16 + g;
        int lr1 = lr0 + 8;
        float zi0 = 1.0f / smZ[lr0];
        float zi1 = 1.0f / smZ[lr1];
        size_t o0 = ((size_t)b * NN + rt + lr0) * HH;
        size_t o1 = ((size_t)b * NN + rt + lr1) * HH;
        #pragma unroll
        for (int nt = 0; nt < 8; ++nt) {
            int col = warpCol * 64 + nt * 8 + qc;
            float c0 = acc[mt][nt][0] * zi0, c1 = acc[mt][nt][1] * zi0;
            float c2 = acc[mt][nt][2] * zi1, c3 = acc[mt][nt][3] * zi1;
            float2 r0, r1;
            r0.x = (c0 > 0.0f) ? c0 : expm1f(c0);
            r0.y = (c1 > 0.0f) ? c1 : expm1f(c1);
            r1.x = (c2 > 0.0f) ? c2 : expm1f(c2);
            r1.y = (c3 > 0.0f) ? c3 : expm1f(c3);
            *(float2*)(out + o0 + col) = r0;
            *(float2*)(out + o1 + col) = r1;
        }
    }
}

// ---------------------------------------------------------------------------
extern "C" void kernel_launch(void* const* d_in, const int* in_sizes, int n_in,
                              void* d_out, int out_size)
{
    const float* inp = (const float*)d_in[0];   // [B,N,H]
    const float* A   = (const float*)d_in[1];   // [B,N,N]
    const int*   l   = (const int*)  d_in[2];   // [B,2]
    const float* Wi  = (const float*)d_in[3];   // [H,H]
    const float* Wc  = (const float*)d_in[4];   // [H,H]
    const float* a   = (const float*)d_in[5];   // [2H,1]
    float* out = (float*)d_out;

    cudaFuncSetAttribute(gemm_kernel, cudaFuncAttributeMaxDynamicSharedMemorySize, SMEM_TOT);
    cudaFuncSetAttribute(fused_attn_kernel, cudaFuncAttributeMaxDynamicSharedMemorySize, FSMEM_TOT);

    wsplit_kernel<<<2 * HH * HH / 256, 256>>>(Wi, Wc);
    gemm_kernel<<<BB * NN / 128, 512, SMEM_TOT>>>(inp, l, a);
    fused_attn_kernel<<<BB * NN / 128, 512, FSMEM_TOT>>>(A, out);
}

// round 13
// speedup vs baseline: 1.6675x; 1.6675x over previous
#include <cuda_runtime.h>
#include <cuda_fp16.h>
#include <cuda_bf16.h>
#include <math.h>
#include <stdint.h>

#define BB 32
#define NN 1024
#define HH 256

// Scratch (__device__ globals; no allocations allowed)
static __device__ __half        g_WhH[BB * NN * HH];   // 16 MB fp16 Wh
static __device__ __half        g_att[BB * NN * NN];   // 64 MB fp16 dense normalized att
static __device__ float         g_s1[BB * NN];
static __device__ float         g_s2[BB * NN];
static __device__ __nv_bfloat16 g_WT[4][HH * HH];      // WiH, WiL, WcH, WcL, transposed [n][k]

// ---------------------------------------------------------------------------
__device__ __forceinline__ uint32_t smem_u32(const void* p) {
    uint32_t a;
    asm("{ .reg .u64 t; cvta.to.shared.u64 t, %1; cvt.u32.u64 %0, t; }" : "=r"(a) : "l"(p));
    return a;
}

#define LDSM_X4(r0, r1, r2, r3, addr) \
    asm volatile("ldmatrix.sync.aligned.m8n8.x4.shared.b16 {%0,%1,%2,%3}, [%4];" \
                 : "=r"(r0), "=r"(r1), "=r"(r2), "=r"(r3) : "r"(addr))

#define LDSM_X4_T(r0, r1, r2, r3, addr) \
    asm volatile("ldmatrix.sync.aligned.m8n8.x4.trans.shared.b16 {%0,%1,%2,%3}, [%4];" \
                 : "=r"(r0), "=r"(r1), "=r"(r2), "=r"(r3) : "r"(addr))

#define MMA_BF16(d, a, b0r, b1r) \
    asm volatile("mma.sync.aligned.m16n8k16.row.col.f32.bf16.bf16.f32 " \
                 "{%0,%1,%2,%3}, {%4,%5,%6,%7}, {%8,%9}, {%0,%1,%2,%3};" \
                 : "+f"((d)[0]), "+f"((d)[1]), "+f"((d)[2]), "+f"((d)[3]) \
                 : "r"((a)[0]), "r"((a)[1]), "r"((a)[2]), "r"((a)[3]), \
                   "r"(b0r), "r"(b1r))

#define MMA_F16(d, a, b0r, b1r) \
    asm volatile("mma.sync.aligned.m16n8k16.row.col.f32.f16.f16.f32 " \
                 "{%0,%1,%2,%3}, {%4,%5,%6,%7}, {%8,%9}, {%0,%1,%2,%3};" \
                 : "+f"((d)[0]), "+f"((d)[1]), "+f"((d)[2]), "+f"((d)[3]) \
                 : "r"((a)[0]), "r"((a)[1]), "r"((a)[2]), "r"((a)[3]), \
                   "r"(b0r), "r"(b1r))

#define CP16(dst, src) \
    asm volatile("cp.async.cg.shared.global [%0], [%1], 16;" :: "r"(dst), "l"(src))
#define CP_COMMIT() asm volatile("cp.async.commit_group;" ::: "memory")

// ---------------------------------------------------------------------------
// Kernel 0: split W_i/W_c into transposed bf16 hi/lo: WT[n][k] = W[k][n]
// ---------------------------------------------------------------------------
__global__ __launch_bounds__(256) void wsplit_kernel(
    const float* __restrict__ Wi, const float* __restrict__ Wc)
{
    int idx = blockIdx.x * 256 + threadIdx.x;
    int which = idx >> 16;
    int e = idx & 65535;
    int n = e >> 8, k = e & 255;
    const float* W = which ? Wc : Wi;
    float x = W[k * HH + n];
    __nv_bfloat16 h = __float2bfloat16(x);
    __nv_bfloat16 lo = __float2bfloat16(x - __bfloat162float(h));
    g_WT[which * 2][n * HH + k] = h;
    g_WT[which * 2 + 1][n * HH + k] = lo;
}

// ---------------------------------------------------------------------------
// Kernel 1 (r11-validated, unchanged): mma.sync bf16 3-term split GEMM,
// 128x256 per CTA, 512 threads, double-buffered smem + register prefetch.
// Fused s1/s2 dots + fp16 Wh store.
// ---------------------------------------------------------------------------
#define PADK 40
#define ABUF (2 * 128 * PADK * 2)
#define BBUF (2 * 256 * PADK * 2)
#define OFF_A   0
#define OFF_B   (2 * ABUF)
#define OFF_AV  (OFF_B + 2 * BBUF)
#define OFF_RED (OFF_AV + 512 * 4)
#define SMEM_TOT (OFF_RED + 4 * 128 * 2 * 4)

__global__ __launch_bounds__(512) void gemm_kernel(
    const float* __restrict__ inp, const int* __restrict__ l,
    const float* __restrict__ avec)
{
    extern __shared__ char smem[];
    const uint32_t sbA = smem_u32(smem) + OFF_A;
    const uint32_t sbB = smem_u32(smem) + OFF_B;
    float* sAv  = (float*)(smem + OFF_AV);
    float* sRed = (float*)(smem + OFF_RED);

    const int tid = threadIdx.x, lane = tid & 31, wid = tid >> 5;
    const int warpRow = wid >> 2, warpCol = wid & 3;
    const int rowTile = blockIdx.x * 128;
    const int b = rowTile >> 10;
    const int n0 = rowTile & 1023;
    const int l0 = l[2 * b], l1 = l[2 * b + 1];
    const bool mixed = (l0 > n0 && l0 < n0 + 128) || (l1 > n0 && l1 < n0 + 128);
    const bool sel0  = (n0 >= l0 && n0 < l1);
    const int npass  = mixed ? 2 : 1;

    sAv[tid] = avec[tid];

    for (int pass = 0; pass < npass; ++pass) {
        const bool useWi = mixed ? (pass == 0) : sel0;
        const __nv_bfloat16* __restrict__ Bh = g_WT[useWi ? 0 : 2];
        const __nv_bfloat16* __restrict__ Bl = g_WT[useWi ? 1 : 3];

        float acc[2][8][4];
        #pragma unroll
        for (int mt = 0; mt < 2; ++mt)
            #pragma unroll
            for (int nt = 0; nt < 8; ++nt)
                #pragma unroll
                for (int e = 0; e < 4; ++e) acc[mt][nt][e] = 0.0f;

        float4 aReg[2];
        int4   bhReg[2], blReg[2];

        auto load_regs = [&](int kc) {
            const int k0 = kc * 32;
            #pragma unroll
            for (int it = 0; it < 2; ++it) {
                int f = tid + it * 512;
                int r = f >> 3, c4 = (f & 7) * 4;
                aReg[it] = *(const float4*)(inp + (size_t)(rowTile + r) * HH + k0 + c4);
            }
            #pragma unroll
            for (int it = 0; it < 2; ++it) {
                int gI = tid + it * 512;
                int r = gI >> 2, c8 = (gI & 3) * 8;
                bhReg[it] = *(const int4*)(Bh + (size_t)r * HH + k0 + c8);
                blReg[it] = *(const int4*)(Bl + (size_t)r * HH + k0 + c8);
            }
        };

        load_regs(0);

        for (int kc = 0; kc < 8; ++kc) {
            const int s = kc & 1;
            const uint32_t aS = sbA + (uint32_t)s * ABUF;
            const uint32_t bS = sbB + (uint32_t)s * BBUF;

            #pragma unroll
            for (int it = 0; it < 2; ++it) {
                int f = tid + it * 512;
                int r = f >> 3, c4 = (f & 7) * 4;
                float xv[4] = {aReg[it].x, aReg[it].y, aReg[it].z, aReg[it].w};
                unsigned short h[4], q[4];
                #pragma unroll
                for (int e = 0; e < 4; ++e) {
                    __nv_bfloat16 bh = __float2bfloat16(xv[e]);
                    h[e] = __bfloat16_as_ushort(bh);
                    q[e] = __bfloat16_as_ushort(
                        __float2bfloat16(xv[e] - __bfloat162float(bh)));
                }
                uint2 hv = make_uint2(h[0] | ((uint32_t)h[1] << 16),
                                      h[2] | ((uint32_t)h[3] << 16));
                uint2 lv = make_uint2(q[0] | ((uint32_t)q[1] << 16),
                                      q[2] | ((uint32_t)q[3] << 16));
                *(uint2*)(smem + OFF_A + s * ABUF + ((size_t)r * PADK + c4) * 2) = hv;
                *(uint2*)(smem + OFF_A + s * ABUF + ((size_t)(128 + r) * PADK + c4) * 2) = lv;
            }
            #pragma unroll
            for (int it = 0; it < 2; ++it) {
                int gI = tid + it * 512;
                int r = gI >> 2, c8 = (gI & 3) * 8;
                *(int4*)(smem + OFF_B + s * BBUF + ((size_t)r * PADK + c8) * 2) = bhReg[it];
                *(int4*)(smem + OFF_B + s * BBUF + ((size_t)(256 + r) * PADK + c8) * 2) = blReg[it];
            }
            __syncthreads();

            if (kc < 7) load_regs(kc + 1);

            #pragma unroll
            for (int ks = 0; ks < 2; ++ks) {
                const int kk = ks * 16;
                uint32_t ah[2][4], al[2][4];
                #pragma unroll
                for (int mt = 0; mt < 2; ++mt) {
                    int row = warpRow * 32 + mt * 16 + (lane & 15);
                    int kcol = kk + (lane >> 4) * 8;
                    uint32_t ad = aS + (uint32_t)(row * PADK + kcol) * 2;
                    LDSM_X4(ah[mt][0], ah[mt][1], ah[mt][2], ah[mt][3], ad);
                    LDSM_X4(al[mt][0], al[mt][1], al[mt][2], al[mt][3],
                            ad + 128 * PADK * 2);
                }
                #pragma unroll
                for (int p = 0; p < 4; ++p) {
                    int row = warpCol * 64 + p * 16 + (lane & 7) + ((lane >> 4) << 3);
                    int kcol = kk + (((lane >> 3) & 1) << 3);
                    uint32_t bd = bS + (uint32_t)(row * PADK + kcol) * 2;
                    uint32_t bh[4], bl[4];
                    LDSM_X4(bh[0], bh[1], bh[2], bh[3], bd);
                    LDSM_X4(bl[0], bl[1], bl[2], bl[3], bd + 256 * PADK * 2);
                    #pragma unroll
                    for (int mt = 0; mt < 2; ++mt) {
                        MMA_BF16(acc[mt][2 * p],     ah[mt], bh[0], bh[1]);
                        MMA_BF16(acc[mt][2 * p],     al[mt], bh[0], bh[1]);
                        MMA_BF16(acc[mt][2 * p],     ah[mt], bl[0], bl[1]);
                        MMA_BF16(acc[mt][2 * p + 1], ah[mt], bh[2], bh[3]);
                        MMA_BF16(acc[mt][2 * p + 1], al[mt], bh[2], bh[3]);
                        MMA_BF16(acc[mt][2 * p + 1], ah[mt], bl[2], bl[3]);
                    }
                }
            }
        }

        __syncthreads();
        const int g = lane >> 2, qc = (lane & 3) * 2;
        #pragma unroll
        for (int mt = 0; mt < 2; ++mt) {
            int lr0 = warpRow * 32 + mt * 16 + g;
            int lr1 = lr0 + 8;
            int gr0 = rowTile + lr0, gr1 = rowTile + lr1;
            int nr0 = n0 + lr0, nr1 = n0 + lr1;
            bool dw0 = !mixed || (((nr0 >= l0) && (nr0 < l1)) == useWi);
            bool dw1 = !mixed || (((nr1 >= l0) && (nr1 < l1)) == useWi);
            float s1r0 = 0, s2r0 = 0, s1r1 = 0, s2r1 = 0;
            #pragma unroll
            for (int nt = 0; nt < 8; ++nt) {
                int col = warpCol * 64 + nt * 8 + qc;
                float a0 = sAv[col], a1 = sAv[col + 1];
                float b0 = sAv[256 + col], b1 = sAv[256 + col + 1];
                float c0 = acc[mt][nt][0], c1 = acc[mt][nt][1];
                float c2 = acc[mt][nt][2], c3 = acc[mt][nt][3];
                s1r0 = fmaf(c0, a0, fmaf(c1, a1, s1r0));
                s2r0 = fmaf(c0, b0, fmaf(c1, b1, s2r0));
                s1r1 = fmaf(c2, a0, fmaf(c3, a1, s1r1));
                s2r1 = fmaf(c2, b0, fmaf(c3, b1, s2r1));
                if (dw0)
                    *(__half2*)(g_WhH + (size_t)gr0 * HH + col) = __floats2half2_rn(c0, c1);
                if (dw1)
                    *(__half2*)(g_WhH + (size_t)gr1 * HH + col) = __floats2half2_rn(c2, c3);
            }
            #pragma unroll
            for (int d = 1; d <= 2; d <<= 1) {
                s1r0 += __shfl_xor_sync(0xffffffffu, s1r0, d);
                s2r0 += __shfl_xor_sync(0xffffffffu, s2r0, d);
                s1r1 += __shfl_xor_sync(0xffffffffu, s1r1, d);
                s2r1 += __shfl_xor_sync(0xffffffffu, s2r1, d);
            }
            if ((lane & 3) == 0) {
                sRed[(warpCol * 128 + lr0) * 2 + 0] = s1r0;
                sRed[(warpCol * 128 + lr0) * 2 + 1] = s2r0;
                sRed[(warpCol * 128 + lr1) * 2 + 0] = s1r1;
                sRed[(warpCol * 128 + lr1) * 2 + 1] = s2r1;
            }
        }
        __syncthreads();
        if (tid < 128) {
            int grow = rowTile + tid;
            int nrow = n0 + tid;
            bool dw = !mixed || (((nrow >= l0) && (nrow < l1)) == useWi);
            if (dw) {
                float v1 = 0, v2 = 0;
                #pragma unroll
                for (int wc = 0; wc < 4; ++wc) {
                    v1 += sRed[(wc * 128 + tid) * 2 + 0];
                    v2 += sRed[(wc * 128 + tid) * 2 + 1];
                }
                g_s1[grow] = v1;
                g_s2[grow] = v2;
            }
        }
        __syncthreads();
    }
}

// ---------------------------------------------------------------------------
// Kernel 2 (r11-validated, unchanged): masked softmax -> dense fp16 att row.
// ---------------------------------------------------------------------------
__global__ __launch_bounds__(128) void score_kernel(
    const float* __restrict__ A, __half* __restrict__ att)
{
    __shared__ float s_red[8];

    const int bi = blockIdx.x;
    const int b = bi >> 10, i = bi & 1023;
    const int tid = threadIdx.x, lane = tid & 31, w = tid >> 5;
    const float* Arow = A + (size_t)bi * NN;
    const float* s2b = g_s2 + (size_t)b * NN;
    const float s1i = g_s1[bi];

    float av[8];
    {
        float4 v0 = *(const float4*)(Arow + tid * 8);
        float4 v1 = *(const float4*)(Arow + tid * 8 + 4);
        av[0] = v0.x; av[1] = v0.y; av[2] = v0.z; av[3] = v0.w;
        av[4] = v1.x; av[5] = v1.y; av[6] = v1.z; av[7] = v1.w;
    }
    unsigned pbits = 0;
    float xv[8];
    float lmax = -INFINITY;
    #pragma unroll
    for (int q = 0; q < 8; ++q) {
        int j = tid * 8 + q;
        float aval = av[q] + ((j == i) ? 1.0f : 0.0f);   // A + I (diag may be 2)
        if (aval > 0.0f) {
            float x = (s1i + s2b[j]) * aval;
            x = (x > 0.0f) ? x : 0.2f * x;               // leaky relu
            xv[q] = x;
            pbits |= (1u << q);
            lmax = fmaxf(lmax, x);
        }
    }
    float wm = lmax;
    #pragma unroll
    for (int d = 16; d > 0; d >>= 1) wm = fmaxf(wm, __shfl_xor_sync(0xffffffffu, wm, d));
    if (lane == 0) s_red[w] = wm;
    __syncthreads();
    const float m = fmaxf(fmaxf(s_red[0], s_red[1]), fmaxf(s_red[2], s_red[3]));

    float wv[8];
    float lz = 0.0f;
    #pragma unroll
    for (int q = 0; q < 8; ++q) {
        float e = (pbits & (1u << q)) ? __expf(xv[q] - m) : 0.0f;
        wv[q] = e;
        lz += e;
    }
    #pragma unroll
    for (int d = 16; d > 0; d >>= 1) lz += __shfl_xor_sync(0xffffffffu, lz, d);
    if (lane == 0) s_red[4 + w] = lz;
    __syncthreads();
    const float Zi = 1.0f / (s_red[4] + s_red[5] + s_red[6] + s_red[7]);

    __half2 hv[4];
    #pragma unroll
    for (int q = 0; q < 4; ++q)
        hv[q] = __floats2half2_rn(wv[2 * q] * Zi, wv[2 * q + 1] * Zi);
    *(int4*)(att + (size_t)bi * NN + tid * 8) = *(const int4*)hv;
}

// ---------------------------------------------------------------------------
// Kernel 3 v4: out = elu(att @ Wh). 128x256 tile per CTA, 512 threads.
// 3-stage cp.async pipeline, ONE __syncthreads per K-chunk (stage s reused
// only at kc+3; top-of-iter barrier proves chunk kc-1 consumption finished).
// Fragment/ldmatrix/mma code identical to the r10-validated version.
// ---------------------------------------------------------------------------
#define BPADK 72
#define V4_A_STAGE (128 * BPADK * 2)            // 18432
#define V4_B_STAGE (64 * 264 * 2)               // 33792
#define V4_OFF_B   (3 * V4_A_STAGE)             // 55296
#define V4_SMEM    (V4_OFF_B + 3 * V4_B_STAGE)  // 156672

__global__ __launch_bounds__(512) void bmm_kernel(
    const __half* __restrict__ att, const __half* __restrict__ Wh,
    float* __restrict__ out)
{
    extern __shared__ char bsm[];
    const uint32_t aBase = smem_u32(bsm);
    const uint32_t bBase = aBase + V4_OFF_B;

    const int tid = threadIdx.x, lane = tid & 31, wid = tid >> 5;
    const int warpRow = wid >> 2, warpCol = wid & 3;
    const int b  = blockIdx.x >> 3;
    const int rt = (blockIdx.x & 7) * 128;
    const __half* attB = att + ((size_t)b * NN + rt) * NN;
    const __half* WhB  = Wh + (size_t)b * NN * HH;

    float acc[2][8][4];
    #pragma unroll
    for (int mt = 0; mt < 2; ++mt)
        #pragma unroll
        for (int nt = 0; nt < 8; ++nt)
            #pragma unroll
            for (int e = 0; e < 4; ++e) acc[mt][nt][e] = 0.0f;

    auto load_stage = [&](int kc, int s) {
        const int k0 = kc * 64;
        uint32_t aS = aBase + (uint32_t)s * V4_A_STAGE;
        uint32_t bS = bBase + (uint32_t)s * V4_B_STAGE;
        #pragma unroll
        for (int it = 0; it < 2; ++it) {
            int f = tid + it * 512;                 // 0..1023: 128 rows x 8 segs
            int r = f >> 3, c = (f & 7) * 8;
            CP16(aS + (uint32_t)(r * BPADK + c) * 2,
                 attB + (size_t)r * NN + k0 + c);
        }
        #pragma unroll
        for (int it = 0; it < 4; ++it) {
            int f = tid + it * 512;                 // 0..2047: 64 rows x 32 segs
            int r = f >> 5, c = (f & 31) * 8;
            CP16(bS + (uint32_t)(r * 264 + c) * 2,
                 WhB + (size_t)(k0 + r) * HH + c);
        }
        CP_COMMIT();
    };

    load_stage(0, 0);
    load_stage(1, 1);

    int sIdx = 0;
    for (int kc = 0; kc < 16; ++kc) {
        if (kc == 15) {
            asm volatile("cp.async.wait_group 0;" ::: "memory");
        } else {
            asm volatile("cp.async.wait_group 1;" ::: "memory");
        }
        __syncthreads();   // chunk kc ready; everyone done consuming kc-1

        if (kc + 2 < 16) {
            int s2 = sIdx + 2; if (s2 >= 3) s2 -= 3;
            load_stage(kc + 2, s2);
        }

        const uint32_t aS = aBase + (uint32_t)sIdx * V4_A_STAGE;
        const uint32_t bS = bBase + (uint32_t)sIdx * V4_B_STAGE;
        #pragma unroll
        for (int ks = 0; ks < 4; ++ks) {
            const int kk = ks * 16;
            uint32_t a[2][4];
            #pragma unroll
            for (int mt = 0; mt < 2; ++mt) {
                int row = warpRow * 32 + mt * 16 + (lane & 15);
                int kcol = kk + (lane >> 4) * 8;
                LDSM_X4(a[mt][0], a[mt][1], a[mt][2], a[mt][3],
                        aS + (uint32_t)(row * BPADK + kcol) * 2);
            }
            #pragma unroll
            for (int p = 0; p < 4; ++p) {
                int n = warpCol * 64 + p * 16;
                int krow = kk + (lane & 15);
                int col = n + ((lane >> 4) << 3);
                uint32_t bfr[4];
                LDSM_X4_T(bfr[0], bfr[1], bfr[2], bfr[3],
                          bS + (uint32_t)(krow * 264 + col) * 2);
                #pragma unroll
                for (int mt = 0; mt < 2; ++mt) {
                    MMA_F16(acc[mt][2 * p],     a[mt], bfr[0], bfr[1]);
                    MMA_F16(acc[mt][2 * p + 1], a[mt], bfr[2], bfr[3]);
                }
            }
        }

        ++sIdx; if (sIdx == 3) sIdx = 0;
    }

    // ---- epilogue: elu + fp32 store ----
    const int g = lane >> 2, qc = (lane & 3) * 2;
    #pragma unroll
    for (int mt = 0; mt < 2; ++mt) {
        int lr0 = warpRow * 32 + mt * 16 + g;
        int lr1 = lr0 + 8;
        size_t o0 = ((size_t)b * NN + rt + lr0) * HH;
        size_t o1 = ((size_t)b * NN + rt + lr1) * HH;
        #pragma unroll
        for (int nt = 0; nt < 8; ++nt) {
            int col = warpCol * 64 + nt * 8 + qc;
            float c0 = acc[mt][nt][0], c1 = acc[mt][nt][1];
            float c2 = acc[mt][nt][2], c3 = acc[mt][nt][3];
            float2 r0, r1;
            r0.x = (c0 > 0.0f) ? c0 : expm1f(c0);
            r0.y = (c1 > 0.0f) ? c1 : expm1f(c1);
            r1.x = (c2 > 0.0f) ? c2 : expm1f(c2);
            r1.y = (c3 > 0.0f) ? c3 : expm1f(c3);
            *(float2*)(out + o0 + col) = r0;
            *(float2*)(out + o1 + col) = r1;
        }
    }
}

// ---------------------------------------------------------------------------
extern "C" void kernel_launch(void* const* d_in, const int* in_sizes, int n_in,
                              void* d_out, int out_size)
{
    const float* inp = (const float*)d_in[0];   // [B,N,H]
    const float* A   = (const float*)d_in[1];   // [B,N,N]
    const int*   l   = (const int*)  d_in[2];   // [B,2]
    const float* Wi  = (const float*)d_in[3];   // [H,H]
    const float* Wc  = (const float*)d_in[4];   // [H,H]
    const float* a   = (const float*)d_in[5];   // [2H,1]
    float* out = (float*)d_out;

    __half *WhH, *att;
    cudaGetSymbolAddress((void**)&WhH, g_WhH);
    cudaGetSymbolAddress((void**)&att, g_att);

    cudaFuncSetAttribute(gemm_kernel, cudaFuncAttributeMaxDynamicSharedMemorySize, SMEM_TOT);
    cudaFuncSetAttribute(bmm_kernel, cudaFuncAttributeMaxDynamicSharedMemorySize, V4_SMEM);

    wsplit_kernel<<<2 * HH * HH / 256, 256>>>(Wi, Wc);
    gemm_kernel<<<BB * NN / 128, 512, SMEM_TOT>>>(inp, l, a);
    score_kernel<<<BB * NN, 128>>>(A, att);
    bmm_kernel<<<BB * NN / 128, 512, V4_SMEM>>>(att, WhH, out);
}